// round 12
// baseline (speedup 1.0000x reference)
#include <cuda_runtime.h>
#include <cuda_bf16.h>
#include <math.h>

#define N_NODES 50000
#define N_EDGES 800000
#define N_FEAT  128
#define DIM     32
#define N_GRAPHS 500
#define N_CLASSES 2
#define CAP     64            // per-node bin capacity (P(deg>64) ~ 1e-20)

// ---------------- scratch (no allocations allowed) ----------------
// Self-cleaning invariant: g_deg, g_agg, g_pooled are zero at the start of
// every kernel_launch call (zero-init at module load; each consumer kernel
// re-zeroes what it read, restoring the invariant for the next graph replay).
__device__ float g_y[N_NODES * DIM];        // x @ w_rel
__device__ float g_z[N_NODES * DIM];        // x @ w_root
__device__ float g_agg[N_NODES * DIM];      // overflow-fallback accumulator
__device__ float g_pooled[N_GRAPHS * DIM];
__device__ int   g_deg[N_NODES];
__device__ int2  g_bin[N_NODES * CAP];      // (src, weight bits), 25.6 MB

// packed f32x2 fma: acc = a * b + acc
#define FMA2(acc, a, b) \
    asm("fma.rn.f32x2 %0, %1, %2, %0;" : "+l"(acc) : "l"(a), "l"(b))

__device__ __forceinline__ float f32x2_hsum(unsigned long long v) {
    unsigned lo, hi;
    asm("mov.b64 {%0,%1}, %2;" : "=r"(lo), "=r"(hi) : "l"(v));
    return __uint_as_float(lo) + __uint_as_float(hi);
}

__device__ __forceinline__ unsigned long long f32x2_pack(float a, float b) {
    unsigned long long r;
    asm("mov.b64 %0, {%1,%2};" : "=l"(r) : "r"(__float_as_uint(a)), "r"(__float_as_uint(b)));
    return r;
}

// ---------------- kernel 1: projection, double-buffered (1 bar/iter) ----
// 8 warps = 2 quads; each quad owns 16 nodes; each warp owns a 32-wide
// k-slice with weight pairs in registers. Partials go through a 2-slot smem
// buffer: one barrier per iteration; iteration i+1's x loads overlap the
// reduce of iteration i.
__global__ void __launch_bounds__(256) proj_kernel(const float* __restrict__ x,
                            const float* __restrict__ w_rel,
                            const float* __restrict__ w_root) {
    __shared__ float s_part[2][2][4][2][DIM];   // [buf][quad][kq][y/z][lane]
    int tid  = threadIdx.x;
    int lane = tid & 31;
    int warp = tid >> 5;
    int quad = warp >> 2;
    int kq   = warp & 3;

    unsigned long long wpy[16], wpz[16];
#pragma unroll
    for (int p = 0; p < 16; p++) {
        int k0 = (kq * 32 + 2 * p) * DIM + lane;
        wpy[p] = f32x2_pack(w_rel [k0], w_rel [k0 + DIM]);
        wpz[p] = f32x2_pack(w_root[k0], w_root[k0 + DIM]);
    }

    int base = blockIdx.x * 32;

#pragma unroll 1
    for (int it = 0; it < 16; ++it) {
        int buf  = it & 1;
        int node = base + quad * 16 + it;
        unsigned long long accY = 0ull, accZ = 0ull;
        if (node < N_NODES) {
            const ulonglong2* xp = reinterpret_cast<const ulonglong2*>(
                x + (size_t)node * N_FEAT + kq * 32);
            ulonglong2 xv[8];
#pragma unroll
            for (int j = 0; j < 8; j++) xv[j] = xp[j];   // uniform broadcast
#pragma unroll
            for (int j = 0; j < 8; j++) {
                FMA2(accY, xv[j].x, wpy[2 * j]);
                FMA2(accZ, xv[j].x, wpz[2 * j]);
                FMA2(accY, xv[j].y, wpy[2 * j + 1]);
                FMA2(accZ, xv[j].y, wpz[2 * j + 1]);
            }
        }
        s_part[buf][quad][kq][0][lane] = f32x2_hsum(accY);
        s_part[buf][quad][kq][1][lane] = f32x2_hsum(accZ);
        __syncthreads();                      // ONE barrier per iteration

        // reduce this iteration's buffer; other warps run ahead into the
        // next iteration's loads (they write the other buffer).
        if (warp < 4) {
            int nq  = warp >> 1;
            int out = warp & 1;
            int n2  = base + nq * 16 + it;
            if (n2 < N_NODES) {
                float v = s_part[buf][nq][0][out][lane] + s_part[buf][nq][1][out][lane]
                        + s_part[buf][nq][2][out][lane] + s_part[buf][nq][3][out][lane];
                if (out == 0) g_y[n2 * DIM + lane] = v;
                else          g_z[n2 * DIM + lane] = v;
            }
        }
    }
}

// ---------------- inline dtype detection helper -------------------------
// int64 little-endian: every odd 32-bit word is hi word of an id<50000 -> 0.
__device__ __forceinline__ bool detect_is64(const int* __restrict__ ei_raw,
                                            int tid) {
    int probe = ei_raw[(tid & 255) * 2 + 1];
    int nz = __syncthreads_count(probe != 0);
    return nz == 0;
}

// ---------------- kernel 2: binned fill (1 edge/thread, R8 version) -----
__global__ void __launch_bounds__(256) fill_kernel(const int* __restrict__ ei_raw,
                            const float* __restrict__ ew) {
    bool is64 = detect_is64(ei_raw, threadIdx.x);
    int e = blockIdx.x * 256 + threadIdx.x;
    if (e >= N_EDGES) return;

    int src, dst;
    if (is64) {
        src = ei_raw[2 * e];
        dst = ei_raw[2 * (N_EDGES + e)];
    } else {
        src = ei_raw[e];
        dst = ei_raw[N_EDGES + e];
    }
    float w = ew[e];                         // issue before the atomic
    if ((unsigned)src >= N_NODES || (unsigned)dst >= N_NODES) return;

    int pos = atomicAdd(&g_deg[dst], 1);
    if (pos < CAP) {
        g_bin[dst * CAP + pos] = make_int2(src, __float_as_int(w));
    } else {
        // astronomically rare overflow: direct reduction into g_agg
        const float4* yp = reinterpret_cast<const float4*>(g_y) + src * 8;
        float4* ap = reinterpret_cast<float4*>(g_agg) + dst * 8;
#pragma unroll
        for (int s = 0; s < 8; s++) {
            float4 v = yp[s];
            asm volatile("red.global.add.v4.f32 [%0], {%1,%2,%3,%4};"
                         :: "l"(ap + s), "f"(v.x*w), "f"(v.y*w), "f"(v.z*w), "f"(v.w*w)
                         : "memory");
        }
    }
}

// ---------------- kernel 3: gather + relu + pool + self-clean -----------
__global__ void __launch_bounds__(256) gather_kernel(const float* __restrict__ b_rel,
                              const int* __restrict__ batch_raw,
                              const int* __restrict__ ei_raw) {
    bool is64 = detect_is64(ei_raw, threadIdx.x);
    int warp = threadIdx.x >> 5;
    int lane = threadIdx.x & 31;
    int node = blockIdx.x * 8 + warp;
    if (node >= N_NODES) return;

    int deg = g_deg[node];
    if (lane == 0) g_deg[node] = 0;          // restore invariant for next replay
    if (deg > CAP) deg = CAP;

    const int4* bp = reinterpret_cast<const int4*>(g_bin + node * CAP);

    float acc = g_agg[node * DIM + lane];    // overflow fallback (usually 0)
    g_agg[node * DIM + lane] = 0.0f;         // restore invariant

    int i = 0;
    for (; i + 7 < deg; i += 8) {            // 4 int4 loads = 8 edges in flight
        int4 p0 = bp[(i >> 1) + 0];
        int4 p1 = bp[(i >> 1) + 1];
        int4 p2 = bp[(i >> 1) + 2];
        int4 p3 = bp[(i >> 1) + 3];
        float y0 = g_y[p0.x * DIM + lane];
        float y1 = g_y[p0.z * DIM + lane];
        float y2 = g_y[p1.x * DIM + lane];
        float y3 = g_y[p1.z * DIM + lane];
        float y4 = g_y[p2.x * DIM + lane];
        float y5 = g_y[p2.z * DIM + lane];
        float y6 = g_y[p3.x * DIM + lane];
        float y7 = g_y[p3.z * DIM + lane];
        acc = fmaf(__int_as_float(p0.y), y0, acc);
        acc = fmaf(__int_as_float(p0.w), y1, acc);
        acc = fmaf(__int_as_float(p1.y), y2, acc);
        acc = fmaf(__int_as_float(p1.w), y3, acc);
        acc = fmaf(__int_as_float(p2.y), y4, acc);
        acc = fmaf(__int_as_float(p2.w), y5, acc);
        acc = fmaf(__int_as_float(p3.y), y6, acc);
        acc = fmaf(__int_as_float(p3.w), y7, acc);
    }
    for (; i + 1 < deg; i += 2) {
        int4 p0 = bp[i >> 1];
        float y0 = g_y[p0.x * DIM + lane];
        float y1 = g_y[p0.z * DIM + lane];
        acc = fmaf(__int_as_float(p0.y), y0, acc);
        acc = fmaf(__int_as_float(p0.w), y1, acc);
    }
    if (i < deg) {
        int2 e0 = g_bin[node * CAP + i];
        acc = fmaf(__int_as_float(e0.y), g_y[e0.x * DIM + lane], acc);
    }

    float h = fmaxf(acc + g_z[node * DIM + lane] + b_rel[lane], 0.0f);

    int g = is64 ? batch_raw[2 * node] : batch_raw[node];
    if ((unsigned)g < N_GRAPHS)
        atomicAdd(&g_pooled[g * DIM + lane], h);
}

// ---------------- kernel 4: head MLP + log_softmax + self-clean ---------
__global__ void __launch_bounds__(256) head_kernel(const float* __restrict__ w_fc1,
                            const float* __restrict__ b_fc1,
                            const float* __restrict__ w_fc2,
                            const float* __restrict__ b_fc2,
                            float* __restrict__ out) {
    int warp = threadIdx.x >> 5;
    int lane = threadIdx.x & 31;
    int g = blockIdx.x * 8 + warp;
    if (g >= N_GRAPHS) return;

    float p = g_pooled[g * DIM + lane];
    g_pooled[g * DIM + lane] = 0.0f;         // restore invariant for next replay

    float acc = b_fc1[lane];
#pragma unroll
    for (int j = 0; j < DIM; j++) {
        float pj = __shfl_sync(0xffffffffu, p, j);
        acc = fmaf(pj, w_fc1[j * DIM + lane], acc);
    }
    float h2 = fmaxf(acc, 0.0f);

    float2 wv = reinterpret_cast<const float2*>(w_fc2)[lane];
    float l0 = h2 * wv.x;
    float l1 = h2 * wv.y;
#pragma unroll
    for (int o = 16; o > 0; o >>= 1) {
        l0 += __shfl_xor_sync(0xffffffffu, l0, o);
        l1 += __shfl_xor_sync(0xffffffffu, l1, o);
    }

    if (lane == 0) {
        l0 += b_fc2[0];
        l1 += b_fc2[1];
        float m = fmaxf(l0, l1);
        float lse = m + logf(expf(l0 - m) + expf(l1 - m));
        out[g * 2 + 0] = l0 - lse;
        out[g * 2 + 1] = l1 - lse;
    }
}

extern "C" void kernel_launch(void* const* d_in, const int* in_sizes, int n_in,
                              void* d_out, int out_size) {
    const float* x      = (const float*)d_in[0];
    const float* ew     = (const float*)d_in[1];
    const float* w_rel  = (const float*)d_in[2];
    const float* b_rel  = (const float*)d_in[3];
    const float* w_root = (const float*)d_in[4];
    const float* w_fc1  = (const float*)d_in[5];
    const float* b_fc1  = (const float*)d_in[6];
    const float* w_fc2  = (const float*)d_in[7];
    const float* b_fc2  = (const float*)d_in[8];
    const int*   ei     = (const int*)d_in[9];
    const int*   batch  = (const int*)d_in[10];
    float* out = (float*)d_out;

    static cudaStream_t s2 = 0;
    static cudaEvent_t evA = 0, evB = 0;
    if (!s2) {
        cudaStreamCreateWithFlags(&s2, cudaStreamNonBlocking);
        cudaEventCreateWithFlags(&evA, cudaEventDisableTiming);
        cudaEventCreateWithFlags(&evB, cudaEventDisableTiming);
    }

    // fork: side stream runs fill (g_deg already zero: self-cleaning),
    // main stream runs proj. Disjoint data.
    cudaEventRecord(evA, 0);
    cudaStreamWaitEvent(s2, evA, 0);

    proj_kernel<<<(N_NODES + 31) / 32, 256>>>(x, w_rel, w_root);

    fill_kernel<<<(N_EDGES + 255) / 256, 256, 0, s2>>>(ei, ew);

    // join
    cudaEventRecord(evB, s2);
    cudaStreamWaitEvent(0, evB, 0);

    gather_kernel<<<(N_NODES + 7) / 8, 256>>>(b_rel, batch, ei);
    head_kernel<<<(N_GRAPHS + 7) / 8, 256>>>(w_fc1, b_fc1, w_fc2, b_fc2, out);
}

// round 14
// speedup vs baseline: 2.1128x; 2.1128x over previous
#include <cuda_runtime.h>
#include <cuda_bf16.h>
#include <math.h>

#define N_NODES 50000
#define N_EDGES 800000
#define N_FEAT  128
#define DIM     32
#define N_GRAPHS 500
#define N_CLASSES 2
#define CAP     64            // per-node bin capacity (P(deg>64) ~ 1e-20)

// ---------------- scratch (no allocations allowed) ----------------
__device__ float g_y[N_NODES * DIM];        // x @ w_rel
__device__ float g_z[N_NODES * DIM];        // x @ w_root
__device__ float g_agg[N_NODES * DIM];      // overflow-fallback accumulator
__device__ float g_pooled[N_GRAPHS * DIM];
__device__ int   g_deg[N_NODES];
__device__ int2  g_bin[N_NODES * CAP];      // (src, weight bits), 25.6 MB

// packed f32x2 fma: acc = a * b + acc
#define FMA2(acc, a, b) \
    asm("fma.rn.f32x2 %0, %1, %2, %0;" : "+l"(acc) : "l"(a), "l"(b))

__device__ __forceinline__ float f32x2_hsum(unsigned long long v) {
    unsigned lo, hi;
    asm("mov.b64 {%0,%1}, %2;" : "=r"(lo), "=r"(hi) : "l"(v));
    return __uint_as_float(lo) + __uint_as_float(hi);
}

__device__ __forceinline__ unsigned long long f32x2_pack(float a, float b) {
    unsigned long long r;
    asm("mov.b64 %0, {%1,%2};" : "=l"(r) : "r"(__float_as_uint(a)), "r"(__float_as_uint(b)));
    return r;
}

// ---------------- kernel Z: zero scratch (runs on side stream) ----------
__global__ void __launch_bounds__(256) zero_kernel() {
    int i = blockIdx.x * 256 + threadIdx.x;
    if (i < N_NODES * DIM / 4)
        reinterpret_cast<float4*>(g_agg)[i] = make_float4(0.f, 0.f, 0.f, 0.f);
    if (i < N_NODES) g_deg[i] = 0;
    if (i < N_GRAPHS * DIM) g_pooled[i] = 0.0f;
}

// ---------------- kernel 1: projection (f32x2, weights in registers) ----
#define NODES_PER_QUAD 16
__global__ void __launch_bounds__(256) proj_kernel(const float* __restrict__ x,
                            const float* __restrict__ w_rel,
                            const float* __restrict__ w_root) {
    __shared__ float s_part[2][4][2][DIM];   // [quad][kq][y/z][lane]
    int tid  = threadIdx.x;
    int lane = tid & 31;
    int warp = tid >> 5;
    int quad = warp >> 2;
    int kq   = warp & 3;

    unsigned long long wpy[16], wpz[16];
#pragma unroll
    for (int p = 0; p < 16; p++) {
        int k0 = (kq * 32 + 2 * p) * DIM + lane;
        wpy[p] = f32x2_pack(w_rel [k0], w_rel [k0 + DIM]);
        wpz[p] = f32x2_pack(w_root[k0], w_root[k0 + DIM]);
    }

    int base = blockIdx.x * (2 * NODES_PER_QUAD);

#pragma unroll 1
    for (int it = 0; it < NODES_PER_QUAD; ++it) {
        int node = base + quad * NODES_PER_QUAD + it;
        unsigned long long accY = 0ull, accZ = 0ull;
        if (node < N_NODES) {
            const ulonglong2* xp = reinterpret_cast<const ulonglong2*>(
                x + (size_t)node * N_FEAT + kq * 32);
            ulonglong2 xv[8];
#pragma unroll
            for (int j = 0; j < 8; j++) xv[j] = xp[j];   // uniform broadcast
#pragma unroll
            for (int j = 0; j < 8; j++) {
                FMA2(accY, xv[j].x, wpy[2 * j]);
                FMA2(accZ, xv[j].x, wpz[2 * j]);
                FMA2(accY, xv[j].y, wpy[2 * j + 1]);
                FMA2(accZ, xv[j].y, wpz[2 * j + 1]);
            }
        }
        s_part[quad][kq][0][lane] = f32x2_hsum(accY);
        s_part[quad][kq][1][lane] = f32x2_hsum(accZ);
        __syncthreads();

        if (warp < 4) {
            int nq  = warp >> 1;
            int out = warp & 1;
            int n2  = base + nq * NODES_PER_QUAD + it;
            if (n2 < N_NODES) {
                float v = s_part[nq][0][out][lane] + s_part[nq][1][out][lane]
                        + s_part[nq][2][out][lane] + s_part[nq][3][out][lane];
                if (out == 0) g_y[n2 * DIM + lane] = v;
                else          g_z[n2 * DIM + lane] = v;
            }
        }
        __syncthreads();
    }
}

// ---------------- inline dtype detection helper -------------------------
__device__ __forceinline__ bool detect_is64(const int* __restrict__ ei_raw,
                                            int tid) {
    int probe = ei_raw[(tid & 255) * 2 + 1];
    int nz = __syncthreads_count(probe != 0);
    return nz == 0;
}

// ---------------- kernel 2: binned fill (1 edge/thread) -----------------
__global__ void __launch_bounds__(256) fill_kernel(const int* __restrict__ ei_raw,
                            const float* __restrict__ ew) {
    bool is64 = detect_is64(ei_raw, threadIdx.x);
    int e = blockIdx.x * 256 + threadIdx.x;
    if (e >= N_EDGES) return;

    int src, dst;
    if (is64) {
        src = ei_raw[2 * e];
        dst = ei_raw[2 * (N_EDGES + e)];
    } else {
        src = ei_raw[e];
        dst = ei_raw[N_EDGES + e];
    }
    float w = ew[e];                         // issue before the atomic
    if ((unsigned)src >= N_NODES || (unsigned)dst >= N_NODES) return;

    int pos = atomicAdd(&g_deg[dst], 1);
    if (pos < CAP) {
        g_bin[dst * CAP + pos] = make_int2(src, __float_as_int(w));
    } else {
        // astronomically rare overflow: direct reduction into g_agg
        const float4* yp = reinterpret_cast<const float4*>(g_y) + src * 8;
        float4* ap = reinterpret_cast<float4*>(g_agg) + dst * 8;
#pragma unroll
        for (int s = 0; s < 8; s++) {
            float4 v = yp[s];
            asm volatile("red.global.add.v4.f32 [%0], {%1,%2,%3,%4};"
                         :: "l"(ap + s), "f"(v.x*w), "f"(v.y*w), "f"(v.z*w), "f"(v.w*w)
                         : "memory");
        }
    }
}

// ---------------- kernel 3: gather + relu + pool (unroll 8) -------------
__global__ void __launch_bounds__(256) gather_kernel(const float* __restrict__ b_rel,
                              const int* __restrict__ batch_raw,
                              const int* __restrict__ ei_raw) {
    bool is64 = detect_is64(ei_raw, threadIdx.x);
    int warp = threadIdx.x >> 5;
    int lane = threadIdx.x & 31;
    int node = blockIdx.x * 8 + warp;
    if (node >= N_NODES) return;

    int deg = g_deg[node];
    if (deg > CAP) deg = CAP;

    const int4* bp = reinterpret_cast<const int4*>(g_bin + node * CAP);

    float acc = g_agg[node * DIM + lane];    // overflow fallback (usually 0)
    int i = 0;
    for (; i + 7 < deg; i += 8) {            // 4 int4 loads = 8 edges in flight
        int4 p0 = bp[(i >> 1) + 0];
        int4 p1 = bp[(i >> 1) + 1];
        int4 p2 = bp[(i >> 1) + 2];
        int4 p3 = bp[(i >> 1) + 3];
        float y0 = g_y[p0.x * DIM + lane];
        float y1 = g_y[p0.z * DIM + lane];
        float y2 = g_y[p1.x * DIM + lane];
        float y3 = g_y[p1.z * DIM + lane];
        float y4 = g_y[p2.x * DIM + lane];
        float y5 = g_y[p2.z * DIM + lane];
        float y6 = g_y[p3.x * DIM + lane];
        float y7 = g_y[p3.z * DIM + lane];
        acc = fmaf(__int_as_float(p0.y), y0, acc);
        acc = fmaf(__int_as_float(p0.w), y1, acc);
        acc = fmaf(__int_as_float(p1.y), y2, acc);
        acc = fmaf(__int_as_float(p1.w), y3, acc);
        acc = fmaf(__int_as_float(p2.y), y4, acc);
        acc = fmaf(__int_as_float(p2.w), y5, acc);
        acc = fmaf(__int_as_float(p3.y), y6, acc);
        acc = fmaf(__int_as_float(p3.w), y7, acc);
    }
    for (; i + 1 < deg; i += 2) {
        int4 p0 = bp[i >> 1];
        float y0 = g_y[p0.x * DIM + lane];
        float y1 = g_y[p0.z * DIM + lane];
        acc = fmaf(__int_as_float(p0.y), y0, acc);
        acc = fmaf(__int_as_float(p0.w), y1, acc);
    }
    if (i < deg) {
        int2 e0 = g_bin[node * CAP + i];
        acc = fmaf(__int_as_float(e0.y), g_y[e0.x * DIM + lane], acc);
    }

    float h = fmaxf(acc + g_z[node * DIM + lane] + b_rel[lane], 0.0f);

    int g = is64 ? batch_raw[2 * node] : batch_raw[node];
    if ((unsigned)g < N_GRAPHS)
        atomicAdd(&g_pooled[g * DIM + lane], h);
}

// ---------------- kernel 4: head MLP + log_softmax (warp per graph) -----
__global__ void __launch_bounds__(256) head_kernel(const float* __restrict__ w_fc1,
                            const float* __restrict__ b_fc1,
                            const float* __restrict__ w_fc2,
                            const float* __restrict__ b_fc2,
                            float* __restrict__ out) {
    int warp = threadIdx.x >> 5;
    int lane = threadIdx.x & 31;
    int g = blockIdx.x * 8 + warp;
    if (g >= N_GRAPHS) return;

    float p = g_pooled[g * DIM + lane];

    float acc = b_fc1[lane];
#pragma unroll
    for (int j = 0; j < DIM; j++) {
        float pj = __shfl_sync(0xffffffffu, p, j);
        acc = fmaf(pj, w_fc1[j * DIM + lane], acc);
    }
    float h2 = fmaxf(acc, 0.0f);

    float2 wv = reinterpret_cast<const float2*>(w_fc2)[lane];
    float l0 = h2 * wv.x;
    float l1 = h2 * wv.y;
#pragma unroll
    for (int o = 16; o > 0; o >>= 1) {
        l0 += __shfl_xor_sync(0xffffffffu, l0, o);
        l1 += __shfl_xor_sync(0xffffffffu, l1, o);
    }

    if (lane == 0) {
        l0 += b_fc2[0];
        l1 += b_fc2[1];
        float m = fmaxf(l0, l1);
        float lse = m + logf(expf(l0 - m) + expf(l1 - m));
        out[g * 2 + 0] = l0 - lse;
        out[g * 2 + 1] = l1 - lse;
    }
}

extern "C" void kernel_launch(void* const* d_in, const int* in_sizes, int n_in,
                              void* d_out, int out_size) {
    const float* x      = (const float*)d_in[0];
    const float* ew     = (const float*)d_in[1];
    const float* w_rel  = (const float*)d_in[2];
    const float* b_rel  = (const float*)d_in[3];
    const float* w_root = (const float*)d_in[4];
    const float* w_fc1  = (const float*)d_in[5];
    const float* b_fc1  = (const float*)d_in[6];
    const float* w_fc2  = (const float*)d_in[7];
    const float* b_fc2  = (const float*)d_in[8];
    const int*   ei     = (const int*)d_in[9];
    const int*   batch  = (const int*)d_in[10];
    float* out = (float*)d_out;

    static cudaStream_t s2 = 0;
    static cudaEvent_t evA = 0, evB = 0;
    if (!s2) {
        cudaStreamCreateWithFlags(&s2, cudaStreamNonBlocking);
        cudaEventCreateWithFlags(&evA, cudaEventDisableTiming);
        cudaEventCreateWithFlags(&evB, cudaEventDisableTiming);
    }

    // fork: side stream does zero -> fill, main stream does proj
    cudaEventRecord(evA, 0);
    cudaStreamWaitEvent(s2, evA, 0);

    proj_kernel<<<(N_NODES + 2 * NODES_PER_QUAD - 1) / (2 * NODES_PER_QUAD), 256>>>(x, w_rel, w_root);

    zero_kernel<<<(N_NODES * DIM / 4 + 255) / 256, 256, 0, s2>>>();
    fill_kernel<<<(N_EDGES + 255) / 256, 256, 0, s2>>>(ei, ew);

    // join
    cudaEventRecord(evB, s2);
    cudaStreamWaitEvent(0, evB, 0);

    gather_kernel<<<(N_NODES + 7) / 8, 256>>>(b_rel, batch, ei);
    head_kernel<<<(N_GRAPHS + 7) / 8, 256>>>(w_fc1, b_fc1, w_fc2, b_fc2, out);
}